// round 1
// baseline (speedup 1.0000x reference)
#include <cuda_runtime.h>
#include <cuda_bf16.h>
#include <math.h>

// Problem constants: B=8, N=1024, Fin=512, Fout=512, H=8, dh=64
#define BATCH 8
#define NN    1024
#define FIN   512
#define FOUT  512
#define HEADS 8
#define DH    64
#define ALPHA_LR 0.2f
#define NEG_INF_V -9.0e15f

// Scratch (device globals: allocation is forbidden)
__device__ float g_h[BATCH * NN * FOUT];          // 16.8 MB: x@W + b
__device__ float g_ssrc[BATCH * HEADS * NN];      // s_src[b,h,n]
__device__ float g_sdst[BATCH * HEADS * NN];      // s_dst[b,h,n]

// ---------------------------------------------------------------------------
// K1: SGEMM  g_h[8192,512] = X[8192,512] @ W[512,512] + bias
// 128x128x16 tile, 256 threads, 8x8 microtile (4+4 split for bank-conflict-free LDS)
// ---------------------------------------------------------------------------
__global__ __launch_bounds__(256) void gemm_bias_kernel(
    const float* __restrict__ X, const float* __restrict__ W,
    const float* __restrict__ bias)
{
    __shared__ float As[16][132];   // padded, stored transposed: As[k][m]
    __shared__ float Bs[16][128];

    const int bm = blockIdx.y * 128;
    const int bn = blockIdx.x * 128;
    const int tid = threadIdx.x;
    const int tx = tid & 15;
    const int ty = tid >> 4;

    float acc[8][8];
#pragma unroll
    for (int i = 0; i < 8; i++)
#pragma unroll
        for (int j = 0; j < 8; j++) acc[i][j] = 0.f;

    for (int k0 = 0; k0 < FIN; k0 += 16) {
        // load A tile: 128 rows x 16 k  (512 float4)
#pragma unroll
        for (int r = 0; r < 2; r++) {
            int idx = tid + r * 256;
            int row = idx >> 2;
            int kq  = (idx & 3) << 2;
            float4 v = *(const float4*)&X[(bm + row) * FIN + k0 + kq];
            As[kq + 0][row] = v.x;
            As[kq + 1][row] = v.y;
            As[kq + 2][row] = v.z;
            As[kq + 3][row] = v.w;
        }
        // load B tile: 16 k x 128 cols
#pragma unroll
        for (int r = 0; r < 2; r++) {
            int idx = tid + r * 256;
            int krow = idx >> 5;
            int cq   = (idx & 31) << 2;
            *(float4*)&Bs[krow][cq] = *(const float4*)&W[(k0 + krow) * FOUT + bn + cq];
        }
        __syncthreads();

#pragma unroll
        for (int k = 0; k < 16; k++) {
            float a[8], b[8];
            *(float4*)(a)     = *(const float4*)&As[k][ty * 4];
            *(float4*)(a + 4) = *(const float4*)&As[k][64 + ty * 4];
            *(float4*)(b)     = *(const float4*)&Bs[k][tx * 4];
            *(float4*)(b + 4) = *(const float4*)&Bs[k][64 + tx * 4];
#pragma unroll
            for (int i = 0; i < 8; i++)
#pragma unroll
                for (int j = 0; j < 8; j++)
                    acc[i][j] = fmaf(a[i], b[j], acc[i][j]);
        }
        __syncthreads();
    }

    // epilogue: +bias, store
    const int rowsA[2] = { bm + ty * 4, bm + 64 + ty * 4 };
    const int colsA[2] = { bn + tx * 4, bn + 64 + tx * 4 };
#pragma unroll
    for (int ih = 0; ih < 2; ih++) {
#pragma unroll
        for (int ii = 0; ii < 4; ii++) {
            int r = rowsA[ih] + ii;
#pragma unroll
            for (int jh = 0; jh < 2; jh++) {
                float4 bv = *(const float4*)&bias[colsA[jh]];
                float4 o;
                o.x = acc[ih * 4 + ii][jh * 4 + 0] + bv.x;
                o.y = acc[ih * 4 + ii][jh * 4 + 1] + bv.y;
                o.z = acc[ih * 4 + ii][jh * 4 + 2] + bv.z;
                o.w = acc[ih * 4 + ii][jh * 4 + 3] + bv.w;
                *(float4*)&g_h[(size_t)r * FOUT + colsA[jh]] = o;
            }
        }
    }
}

// ---------------------------------------------------------------------------
// K2: attention scores s_src[b,h,n] = sum_d h[b,n,h,d]*att[h,d]
//                     s_dst[b,h,n] = sum_d h[b,n,h,d]*att[h,64+d]
// one block per (b,n), warp per head
// ---------------------------------------------------------------------------
__global__ __launch_bounds__(256) void scores_kernel(const float* __restrict__ att)
{
    const int bn = blockIdx.x;             // 0..8191
    const int b = bn >> 10, n = bn & 1023;
    const int h = threadIdx.x >> 5;
    const int lane = threadIdx.x & 31;

    const float* hrow = g_h + (size_t)bn * FOUT + h * DH;
    const float v0 = hrow[lane];
    const float v1 = hrow[lane + 32];
    const float* at = att + h * (2 * DH);

    float ps = v0 * at[lane] + v1 * at[lane + 32];
    float pd = v0 * at[64 + lane] + v1 * at[96 + lane];
#pragma unroll
    for (int off = 16; off; off >>= 1) {
        ps += __shfl_xor_sync(0xffffffffu, ps, off);
        pd += __shfl_xor_sync(0xffffffffu, pd, off);
    }
    if (lane == 0) {
        g_ssrc[(b * HEADS + h) * NN + n] = ps;
        g_sdst[(b * HEADS + h) * NN + n] = pd;
    }
}

// ---------------------------------------------------------------------------
// K3: fused masked softmax + PV aggregation + ELU
// block = (b, h, 16 rows i); 8 warps, each warp owns 2 rows
// pass1: row max + adj mask bits (32 bits/lane)
// fused pass: p-tile (64 j) into smem, V tile (64x64) staged in smem,
//             acc[d]=sum_j p_j * V[j][d]; normalize + ELU at end.
// ---------------------------------------------------------------------------
__global__ __launch_bounds__(256) void attn_kernel(
    const int* __restrict__ adj, float* __restrict__ out)
{
    __shared__ float ss[NN];            // s_src row for (b,h)
    __shared__ float Vs[64 * 64];       // V tile
    __shared__ float pt[8 * 64 * 2];    // p tile per warp: [w][jj][{row0,row1}]

    const int b = blockIdx.z;
    const int h = blockIdx.y;
    const int i0 = blockIdx.x * 16;
    const int tid = threadIdx.x;
    const int w = tid >> 5;
    const int lane = tid & 31;
    const int bh = b * HEADS + h;

    for (int j = tid; j < NN; j += 256) ss[j] = g_ssrc[bh * NN + j];
    __syncthreads();

    const int iA = i0 + 2 * w;          // warp's first row
    const float sd0 = g_sdst[bh * NN + iA];
    const float sd1 = g_sdst[bh * NN + iA + 1];
    const int* arow0 = adj + (size_t)(b * NN + iA) * NN;
    const int* arow1 = arow0 + NN;

    // pass 1: row max + mask bits
    unsigned mb0 = 0, mb1 = 0;
    float m0 = -3.0e38f, m1 = -3.0e38f;
#pragma unroll 4
    for (int jb = 0; jb < NN; jb += 32) {
        int j = jb + lane;
        float sj = ss[j];
        int a0 = arow0[j];
        int a1 = arow1[j];
        float e0 = sd0 + sj; e0 = (e0 >= 0.f) ? e0 : ALPHA_LR * e0;
        float e1 = sd1 + sj; e1 = (e1 >= 0.f) ? e1 : ALPHA_LR * e1;
        e0 = (a0 > 0) ? e0 : NEG_INF_V;
        e1 = (a1 > 0) ? e1 : NEG_INF_V;
        mb0 |= (a0 > 0) ? (1u << (jb >> 5)) : 0u;
        mb1 |= (a1 > 0) ? (1u << (jb >> 5)) : 0u;
        m0 = fmaxf(m0, e0);
        m1 = fmaxf(m1, e1);
    }
#pragma unroll
    for (int off = 16; off; off >>= 1) {
        m0 = fmaxf(m0, __shfl_xor_sync(0xffffffffu, m0, off));
        m1 = fmaxf(m1, __shfl_xor_sync(0xffffffffu, m1, off));
    }

    float l0 = 0.f, l1 = 0.f;
    float acc00 = 0.f, acc01 = 0.f, acc10 = 0.f, acc11 = 0.f;

    for (int jb = 0; jb < NN; jb += 64) {
        // stage V tile: V[jj][d] = g_h[(b*NN + jb+jj)*FOUT + h*DH + d]
#pragma unroll
        for (int r = 0; r < 4; r++) {
            int idx = tid + r * 256;
            int row = idx >> 4;
            int q = (idx & 15) << 2;
            *(float4*)&Vs[row * 64 + q] =
                *(const float4*)&g_h[(size_t)(b * NN + jb + row) * FOUT + h * DH + q];
        }
        __syncthreads();

        // p tile for this warp's two rows
#pragma unroll
        for (int half = 0; half < 2; half++) {
            int jj = lane + half * 32;
            int j = jb + jj;
            float sj = ss[j];
            unsigned bit = 1u << (j >> 5);
            float e0 = sd0 + sj; e0 = (e0 >= 0.f) ? e0 : ALPHA_LR * e0;
            float e1 = sd1 + sj; e1 = (e1 >= 0.f) ? e1 : ALPHA_LR * e1;
            e0 = (mb0 & bit) ? e0 : NEG_INF_V;
            e1 = (mb1 & bit) ? e1 : NEG_INF_V;
            float p0 = __expf(e0 - m0);
            float p1 = __expf(e1 - m1);
            l0 += p0;
            l1 += p1;
            float2 pv = make_float2(p0, p1);
            *(float2*)&pt[(w * 64 + jj) * 2] = pv;
        }
        __syncwarp();

#pragma unroll 8
        for (int jj = 0; jj < 64; jj++) {
            float2 p = *(const float2*)&pt[(w * 64 + jj) * 2];
            float v0 = Vs[jj * 64 + lane];
            float v1 = Vs[jj * 64 + lane + 32];
            acc00 = fmaf(p.x, v0, acc00);
            acc01 = fmaf(p.x, v1, acc01);
            acc10 = fmaf(p.y, v0, acc10);
            acc11 = fmaf(p.y, v1, acc11);
        }
        __syncthreads();
    }

#pragma unroll
    for (int off = 16; off; off >>= 1) {
        l0 += __shfl_xor_sync(0xffffffffu, l0, off);
        l1 += __shfl_xor_sync(0xffffffffu, l1, off);
    }
    const float r0 = 1.f / l0;
    const float r1 = 1.f / l1;

    size_t base0 = (size_t)(b * NN + iA) * FOUT + h * DH;
    size_t base1 = base0 + FOUT;
    float o;
    o = acc00 * r0; o = (o > 0.f) ? o : expm1f(o); out[base0 + lane]      = o;
    o = acc01 * r0; o = (o > 0.f) ? o : expm1f(o); out[base0 + lane + 32] = o;
    o = acc10 * r1; o = (o > 0.f) ? o : expm1f(o); out[base1 + lane]      = o;
    o = acc11 * r1; o = (o > 0.f) ? o : expm1f(o); out[base1 + lane + 32] = o;
}

// ---------------------------------------------------------------------------
extern "C" void kernel_launch(void* const* d_in, const int* in_sizes, int n_in,
                              void* d_out, int out_size)
{
    const float* x   = (const float*)d_in[0];   // (8,1024,512)
    const int*   adj = (const int*)d_in[1];     // (8,1024,1024)
    const float* Ww  = (const float*)d_in[2];   // (512,512)
    const float* Wb  = (const float*)d_in[3];   // (512,)
    const float* att = (const float*)d_in[4];   // (8,128)
    float* out = (float*)d_out;                 // (8,1024,512)

    gemm_bias_kernel<<<dim3(FOUT / 128, (BATCH * NN) / 128), 256>>>(x, Ww, Wb);
    scores_kernel<<<BATCH * NN, 256>>>(att);
    attn_kernel<<<dim3(NN / 16, HEADS, BATCH), 256>>>(adj, out);
}

// round 2
// speedup vs baseline: 1.9754x; 1.9754x over previous
#include <cuda_runtime.h>
#include <cuda_bf16.h>
#include <math.h>
#include <stdint.h>

// Problem constants: B=8, N=1024, Fin=512, Fout=512, H=8, dh=64
#define BATCH 8
#define NN    1024
#define FIN   512
#define FOUT  512
#define HEADS 8
#define DH    64
#define ALPHA_LR 0.2f

// ---------------- device scratch (no allocation allowed) ----------------
__device__ float         g_h[BATCH * NN * FOUT];     // fp32 h = xW + b
__device__ __nv_bfloat16 g_hh[BATCH * NN * FOUT];    // h hi (bf16)
__device__ __nv_bfloat16 g_hl[BATCH * NN * FOUT];    // h lo (bf16)
__device__ __nv_bfloat16 g_xh[BATCH * NN * FIN];
__device__ __nv_bfloat16 g_xl[BATCH * NN * FIN];
__device__ __nv_bfloat16 g_wh[FIN * FOUT];
__device__ __nv_bfloat16 g_wl[FIN * FOUT];
__device__ float         g_ssrc[BATCH * HEADS * NN];
__device__ float         g_sdst[BATCH * HEADS * NN];
__device__ unsigned      g_adjbits[BATCH * NN * (NN / 32)];

// ---------------- PTX helpers ----------------
static __device__ __forceinline__ uint32_t smem_u32(const void* p) {
    return (uint32_t)__cvta_generic_to_shared(p);
}
static __device__ __forceinline__ void ldsm_x4(uint32_t* r, uint32_t a) {
    asm volatile("ldmatrix.sync.aligned.m8n8.x4.shared.b16 {%0,%1,%2,%3}, [%4];"
        : "=r"(r[0]), "=r"(r[1]), "=r"(r[2]), "=r"(r[3]) : "r"(a));
}
static __device__ __forceinline__ void ldsm_x4_t(uint32_t* r, uint32_t a) {
    asm volatile("ldmatrix.sync.aligned.m8n8.x4.trans.shared.b16 {%0,%1,%2,%3}, [%4];"
        : "=r"(r[0]), "=r"(r[1]), "=r"(r[2]), "=r"(r[3]) : "r"(a));
}
static __device__ __forceinline__ void ldsm_x2_t(uint32_t* r, uint32_t a) {
    asm volatile("ldmatrix.sync.aligned.m8n8.x2.trans.shared.b16 {%0,%1}, [%2];"
        : "=r"(r[0]), "=r"(r[1]) : "r"(a));
}
static __device__ __forceinline__ void mma16816(float* d, const uint32_t* a,
                                                uint32_t b0, uint32_t b1) {
    asm volatile(
        "mma.sync.aligned.m16n8k16.row.col.f32.bf16.bf16.f32 "
        "{%0,%1,%2,%3}, {%4,%5,%6,%7}, {%8,%9}, {%0,%1,%2,%3};"
        : "+f"(d[0]), "+f"(d[1]), "+f"(d[2]), "+f"(d[3])
        : "r"(a[0]), "r"(a[1]), "r"(a[2]), "r"(a[3]), "r"(b0), "r"(b1));
}

// ---------------------------------------------------------------------------
// C0: split X and W into bf16 hi/lo
// ---------------------------------------------------------------------------
__global__ __launch_bounds__(256) void conv_xw(const float* __restrict__ X,
                                               const float* __restrict__ W)
{
    int idx = blockIdx.x * 256 + threadIdx.x;
    const int NX = BATCH * NN * FIN;
    if (idx < NX) {
        float v = X[idx];
        __nv_bfloat16 hi = __float2bfloat16_rn(v);
        g_xh[idx] = hi;
        g_xl[idx] = __float2bfloat16_rn(v - __bfloat162float(hi));
    } else {
        int wi = idx - NX;
        if (wi < FIN * FOUT) {
            float v = W[wi];
            __nv_bfloat16 hi = __float2bfloat16_rn(v);
            g_wh[wi] = hi;
            g_wl[wi] = __float2bfloat16_rn(v - __bfloat162float(hi));
        }
    }
}

// ---------------------------------------------------------------------------
// C1: pack adjacency to bitmask
// ---------------------------------------------------------------------------
__global__ __launch_bounds__(256) void adj_pack(const int* __restrict__ adj)
{
    int e = blockIdx.x * 256 + threadIdx.x;   // 8M elements
    unsigned m = __ballot_sync(0xffffffffu, adj[e] > 0);
    if ((threadIdx.x & 31) == 0) g_adjbits[e >> 5] = m;
}

// ---------------------------------------------------------------------------
// K1: split-bf16 MMA GEMM  h[8192,512] = X[8192,512] @ W[512,512] + b
// K extended to 3 segments: Xh*Wh + Xh*Wl + Xl*Wh
// block 128x128, 8 warps (2m x 4n), warp tile m64 x n32
// ---------------------------------------------------------------------------
__global__ __launch_bounds__(256) void gemm_mma(const float* __restrict__ bias)
{
    __shared__ __align__(16) __nv_bfloat16 As[128 * 40];  // stride 40 (80B)
    __shared__ __align__(16) __nv_bfloat16 Bs[32 * 136];  // stride 136 (272B)

    const int tid = threadIdx.x;
    const int w = tid >> 5, lane = tid & 31;
    const int wm = w >> 2, wn = w & 3;
    const int bm = blockIdx.y * 128, bn = blockIdx.x * 128;

    float acc[4][4][4];
#pragma unroll
    for (int i = 0; i < 4; i++)
#pragma unroll
        for (int j = 0; j < 4; j++)
#pragma unroll
            for (int r = 0; r < 4; r++) acc[i][j][r] = 0.f;

#pragma unroll 1
    for (int seg = 0; seg < 3; seg++) {
        const __nv_bfloat16* Ap = (seg == 2) ? g_xl : g_xh;
        const __nv_bfloat16* Bp = (seg == 1) ? g_wl : g_wh;
#pragma unroll 1
        for (int k0 = 0; k0 < FIN; k0 += 32) {
            __syncthreads();
#pragma unroll
            for (int r = 0; r < 2; r++) {
                int u = tid + r * 256;
                int row = u >> 2, c = u & 3;
                *(uint4*)&As[row * 40 + c * 8] =
                    *(const uint4*)&Ap[(size_t)(bm + row) * FIN + k0 + c * 8];
            }
#pragma unroll
            for (int r = 0; r < 2; r++) {
                int u = tid + r * 256;
                int kr = u >> 4, c = u & 15;
                *(uint4*)&Bs[kr * 136 + c * 8] =
                    *(const uint4*)&Bp[(size_t)(k0 + kr) * FOUT + bn + c * 8];
            }
            __syncthreads();

#pragma unroll
            for (int kc = 0; kc < 2; kc++) {
                uint32_t a[4][4];
#pragma unroll
                for (int mt = 0; mt < 4; mt++) {
                    uint32_t ad = smem_u32(
                        &As[(wm * 64 + mt * 16 + (lane & 15)) * 40 +
                            kc * 16 + (lane >> 4) * 8]);
                    ldsm_x4(a[mt], ad);
                }
                int krow = kc * 16 + (lane & 15);
#pragma unroll
                for (int p = 0; p < 2; p++) {
                    uint32_t b[4];
                    int col = wn * 32 + p * 16 + (lane >> 4) * 8;
                    ldsm_x4_t(b, smem_u32(&Bs[krow * 136 + col]));
#pragma unroll
                    for (int mt = 0; mt < 4; mt++) {
                        mma16816(acc[mt][2 * p],     a[mt], b[0], b[1]);
                        mma16816(acc[mt][2 * p + 1], a[mt], b[2], b[3]);
                    }
                }
            }
        }
    }

    // epilogue: +bias; write fp32 h and bf16 hi/lo
    const int g = lane >> 2, t = lane & 3;
#pragma unroll
    for (int mt = 0; mt < 4; mt++) {
#pragma unroll
        for (int nt = 0; nt < 4; nt++) {
            int col = bn + wn * 32 + nt * 8 + 2 * t;
            float2 bv = *(const float2*)&bias[col];
            float c0 = acc[mt][nt][0] + bv.x;
            float c1 = acc[mt][nt][1] + bv.y;
            float c2 = acc[mt][nt][2] + bv.x;
            float c3 = acc[mt][nt][3] + bv.y;
            size_t r0 = (size_t)(bm + wm * 64 + mt * 16 + g) * FOUT + col;
            size_t r1 = r0 + (size_t)8 * FOUT;
            *(float2*)&g_h[r0] = make_float2(c0, c1);
            *(float2*)&g_h[r1] = make_float2(c2, c3);
            __nv_bfloat162 h0, h1, l0, l1;
            h0.x = __float2bfloat16_rn(c0); h0.y = __float2bfloat16_rn(c1);
            h1.x = __float2bfloat16_rn(c2); h1.y = __float2bfloat16_rn(c3);
            l0.x = __float2bfloat16_rn(c0 - __bfloat162float(h0.x));
            l0.y = __float2bfloat16_rn(c1 - __bfloat162float(h0.y));
            l1.x = __float2bfloat16_rn(c2 - __bfloat162float(h1.x));
            l1.y = __float2bfloat16_rn(c3 - __bfloat162float(h1.y));
            *(__nv_bfloat162*)&g_hh[r0] = h0;
            *(__nv_bfloat162*)&g_hh[r1] = h1;
            *(__nv_bfloat162*)&g_hl[r0] = l0;
            *(__nv_bfloat162*)&g_hl[r1] = l1;
        }
    }
}

// ---------------------------------------------------------------------------
// K2: attention scores (unchanged, reads fp32 g_h)
// ---------------------------------------------------------------------------
__global__ __launch_bounds__(256) void scores_kernel(const float* __restrict__ att)
{
    const int bn = blockIdx.x;
    const int b = bn >> 10, n = bn & 1023;
    const int h = threadIdx.x >> 5;
    const int lane = threadIdx.x & 31;

    const float* hrow = g_h + (size_t)bn * FOUT + h * DH;
    const float v0 = hrow[lane];
    const float v1 = hrow[lane + 32];
    const float* at = att + h * (2 * DH);

    float ps = v0 * at[lane] + v1 * at[lane + 32];
    float pd = v0 * at[64 + lane] + v1 * at[96 + lane];
#pragma unroll
    for (int off = 16; off; off >>= 1) {
        ps += __shfl_xor_sync(0xffffffffu, ps, off);
        pd += __shfl_xor_sync(0xffffffffu, pd, off);
    }
    if (lane == 0) {
        g_ssrc[(b * HEADS + h) * NN + n] = ps;
        g_sdst[(b * HEADS + h) * NN + n] = pd;
    }
}

// ---------------------------------------------------------------------------
// K3: fused masked softmax + PV via split-bf16 MMA + ELU
// block = (b, h, 128 rows). 8 warps, warp owns m16 x n72 (64 data + ones col).
// No max subtraction needed: |e| small; masked -> p = 0 exactly.
// Denominator = MMA against a ones column (col 64).
// ---------------------------------------------------------------------------
__global__ __launch_bounds__(256) void attn_mma(float* __restrict__ out)
{
    __shared__ float ss[NN];
    __shared__ float sdst_s[128];
    __shared__ __align__(16) __nv_bfloat16 Ph[128 * 40];  // stride 40
    __shared__ __align__(16) __nv_bfloat16 Pl[128 * 40];
    __shared__ __align__(16) __nv_bfloat16 Vh[32 * 72];   // stride 72 (144B)
    __shared__ __align__(16) __nv_bfloat16 Vl[32 * 72];

    const int b = blockIdx.z, h = blockIdx.y;
    const int i0 = blockIdx.x * 128;
    const int tid = threadIdx.x;
    const int w = tid >> 5, lane = tid & 31;
    const int bh = b * HEADS + h;

    *(float4*)&ss[tid * 4] = *(const float4*)&g_ssrc[bh * NN + tid * 4];
    if (tid < 128) sdst_s[tid] = g_sdst[bh * NN + i0 + tid];
    // init constant pad columns of V (cols 64..71): col 64 = ones
    {
        int k = tid >> 3, c = 64 + (tid & 7);
        Vh[k * 72 + c] = __float2bfloat16_rn((c == 64) ? 1.0f : 0.0f);
        Vl[k * 72 + c] = __float2bfloat16_rn(0.0f);
    }

    float acc[9][4];
#pragma unroll
    for (int i = 0; i < 9; i++)
#pragma unroll
        for (int r = 0; r < 4; r++) acc[i][r] = 0.f;

    // P-gen mapping: thread handles row pi, 16 j's (half pjh)
    const int pi = tid & 127;
    const int pjh = tid >> 7;
    const unsigned* mrow = g_adjbits + (size_t)(b * NN + i0 + pi) * (NN / 32);

    __syncthreads();
    const float sd = sdst_s[pi];

#pragma unroll 1
    for (int jt = 0; jt < NN / 32; jt++) {
        // stage V tile (cols 0..63 only; pad cols persist)
        {
            int k = tid >> 3, c = tid & 7;
            size_t src = (size_t)(b * NN + jt * 32 + k) * FOUT + h * DH + c * 8;
            *(uint4*)&Vh[k * 72 + c * 8] = *(const uint4*)&g_hh[src];
            *(uint4*)&Vl[k * 72 + c * 8] = *(const uint4*)&g_hl[src];
        }
        // P tile: masked leakyrelu + exp, split to bf16 hi/lo
        {
            const unsigned mw = mrow[jt];
            const int jb = pjh * 16;
#pragma unroll
            for (int q = 0; q < 16; q += 2) {
                float s0 = ss[jt * 32 + jb + q];
                float s1 = ss[jt * 32 + jb + q + 1];
                float e0 = sd + s0; e0 = fmaxf(e0, ALPHA_LR * e0);
                float e1 = sd + s1; e1 = fmaxf(e1, ALPHA_LR * e1);
                float p0 = ((mw >> (jb + q)) & 1u)     ? __expf(e0) : 0.f;
                float p1 = ((mw >> (jb + q + 1)) & 1u) ? __expf(e1) : 0.f;
                __nv_bfloat162 hh, ll;
                hh.x = __float2bfloat16_rn(p0);
                hh.y = __float2bfloat16_rn(p1);
                ll.x = __float2bfloat16_rn(p0 - __bfloat162float(hh.x));
                ll.y = __float2bfloat16_rn(p1 - __bfloat162float(hh.y));
                *(__nv_bfloat162*)&Ph[pi * 40 + jb + q] = hh;
                *(__nv_bfloat162*)&Pl[pi * 40 + jb + q] = ll;
            }
        }
        __syncthreads();

        // MMA phase: warp rows = w*16..+16
#pragma unroll
        for (int kc = 0; kc < 2; kc++) {
            uint32_t ah[4], al[4];
            {
                int arow = (w * 16 + (lane & 15)) * 40 + kc * 16 + (lane >> 4) * 8;
                ldsm_x4(ah, smem_u32(&Ph[arow]));
                ldsm_x4(al, smem_u32(&Pl[arow]));
            }
            const int krow = kc * 16 + (lane & 15);
#pragma unroll
            for (int p = 0; p < 4; p++) {
                uint32_t bhf[4], blf[4];
                int col = p * 16 + (lane >> 4) * 8;
                ldsm_x4_t(bhf, smem_u32(&Vh[krow * 72 + col]));
                ldsm_x4_t(blf, smem_u32(&Vl[krow * 72 + col]));
                mma16816(acc[2 * p],     ah, bhf[0], bhf[1]);
                mma16816(acc[2 * p],     ah, blf[0], blf[1]);
                mma16816(acc[2 * p],     al, bhf[0], bhf[1]);
                mma16816(acc[2 * p + 1], ah, bhf[2], bhf[3]);
                mma16816(acc[2 * p + 1], ah, blf[2], blf[3]);
                mma16816(acc[2 * p + 1], al, bhf[2], bhf[3]);
            }
            // ones column tile (cols 64..71)
            {
                uint32_t b8h[2], b8l[2];
                ldsm_x2_t(b8h, smem_u32(&Vh[krow * 72 + 64]));
                ldsm_x2_t(b8l, smem_u32(&Vl[krow * 72 + 64]));
                mma16816(acc[8], ah, b8h[0], b8h[1]);
                mma16816(acc[8], ah, b8l[0], b8l[1]);
                mma16816(acc[8], al, b8h[0], b8h[1]);
            }
        }
        __syncthreads();
    }

    // normalize + ELU + store
    float den0 = __shfl_sync(0xffffffffu, acc[8][0], lane & 28);
    float den1 = __shfl_sync(0xffffffffu, acc[8][2], lane & 28);
    const float r0 = 1.f / den0;
    const float r1 = 1.f / den1;
    const int g = lane >> 2, t = lane & 3;
    const size_t row0 = (size_t)(b * NN + i0 + w * 16 + g);
    const size_t row1 = row0 + 8;

#pragma unroll
    for (int nt = 0; nt < 8; nt++) {
        int col = h * DH + nt * 8 + 2 * t;
        float o0 = acc[nt][0] * r0; o0 = (o0 > 0.f) ? o0 : expm1f(o0);
        float o1 = acc[nt][1] * r0; o1 = (o1 > 0.f) ? o1 : expm1f(o1);
        float o2 = acc[nt][2] * r1; o2 = (o2 > 0.f) ? o2 : expm1f(o2);
        float o3 = acc[nt][3] * r1; o3 = (o3 > 0.f) ? o3 : expm1f(o3);
        *(float2*)&out[row0 * FOUT + col] = make_float2(o0, o1);
        *(float2*)&out[row1 * FOUT + col] = make_float2(o2, o3);
    }
}

// ---------------------------------------------------------------------------
extern "C" void kernel_launch(void* const* d_in, const int* in_sizes, int n_in,
                              void* d_out, int out_size)
{
    const float* x   = (const float*)d_in[0];   // (8,1024,512)
    const int*   adj = (const int*)d_in[1];     // (8,1024,1024)
    const float* Ww  = (const float*)d_in[2];   // (512,512)
    const float* Wb  = (const float*)d_in[3];   // (512,)
    const float* att = (const float*)d_in[4];   // (8,128)
    float* out = (float*)d_out;                 // (8,1024,512)

    const int nconv = BATCH * NN * FIN + FIN * FOUT;
    conv_xw<<<(nconv + 255) / 256, 256>>>(x, Ww);
    adj_pack<<<(BATCH * NN * NN) / 256, 256>>>(adj);
    gemm_mma<<<dim3(FOUT / 128, (BATCH * NN) / 128), 256>>>(Wb);
    scores_kernel<<<BATCH * NN, 256>>>(att);
    attn_mma<<<dim3(NN / 128, HEADS, BATCH), 256>>>(out);
}